// round 12
// baseline (speedup 1.0000x reference)
#include <cuda_runtime.h>
#include <cuda_fp16.h>

typedef unsigned int u32;

#define B_ 4
#define H_ 16
#define S_ 2048
#define D_ 64
#define NKT 16
#define THREADS 256
#define KQ_STR 36      // u32 per K smem row (144B stride; conflict-free ldmatrix)
#define VT_STR 68      // u32 per Vt smem row (272B stride; conflict-free ldmatrix)

__device__ u32   g_mbits[(size_t)B_ * S_ * (S_ / 32)];     // 2 MB mask bitfield
__device__ float g_inv[(size_t)B_ * H_ * S_];              // per-row 1/sum
__device__ u32   g_ebuf[(size_t)B_ * H_ * S_ * (S_ / 2)];  // 0.54 GB fp16x2 e-buffer
// pre-converted operands, tile-major
__device__ u32   g_khi[(size_t)B_ * H_ * S_ * 32];         // [bh][s][32 u32]
__device__ u32   g_klo[(size_t)B_ * H_ * S_ * 32];
__device__ u32   g_vthi[(size_t)B_ * H_ * NKT * 4096];     // [bh][kt][64 d][64 kp]
__device__ u32   g_vtlo[(size_t)B_ * H_ * NKT * 4096];

#define KBUF   (128 * KQ_STR * 4)
#define SMEM_K (4 * KBUF)                                  // 73728 B -> 2 CTAs/SM
#define VBUF   (64 * VT_STR * 4)
#define SMEM_V (4 * VBUF)                                  // 69632 B -> 2 CTAs/SM

__device__ __forceinline__ void mma16816(float c[4], const u32 a[4], u32 b0, u32 b1) {
    asm volatile("mma.sync.aligned.m16n8k16.row.col.f32.f16.f16.f32 "
                 "{%0,%1,%2,%3}, {%4,%5,%6,%7}, {%8,%9}, {%0,%1,%2,%3};"
                 : "+f"(c[0]), "+f"(c[1]), "+f"(c[2]), "+f"(c[3])
                 : "r"(a[0]), "r"(a[1]), "r"(a[2]), "r"(a[3]), "r"(b0), "r"(b1));
}

__device__ __forceinline__ void ldm4(u32* r, u32 addr) {
    asm volatile("ldmatrix.sync.aligned.m8n8.x4.shared.b16 {%0,%1,%2,%3}, [%4];"
                 : "=r"(r[0]), "=r"(r[1]), "=r"(r[2]), "=r"(r[3]) : "r"(addr));
}

__device__ __forceinline__ u32 smem_u32(const void* p) {
    return (u32)__cvta_generic_to_shared(p);
}

__device__ __forceinline__ void cpa16(u32 dst, const void* src) {
    asm volatile("cp.async.cg.shared.global [%0], [%1], 16;" :: "r"(dst), "l"(src));
}
#define CP_COMMIT() asm volatile("cp.async.commit_group;" ::: "memory")
#define CP_WAIT1()  asm volatile("cp.async.wait_group 1;" ::: "memory")
#define CP_WAIT0()  asm volatile("cp.async.wait_group 0;" ::: "memory")

__device__ __forceinline__ void split2(float x, float y, u32& h, u32& l) {
    __half2 H = __floats2half2_rn(x, y);
    h = *reinterpret_cast<u32*>(&H);
    float2 f = __half22float2(H);
    __half2 L = __floats2half2_rn(x - f.x, y - f.y);
    l = *reinterpret_cast<u32*>(&L);
}
__device__ __forceinline__ u32 pack_h2(float x, float y) {
    __half2 H = __floats2half2_rn(x, y);
    return *reinterpret_cast<u32*>(&H);
}
__device__ __forceinline__ float2 unpack_h2(u32 v) {
    return __half22float2(*reinterpret_cast<__half2*>(&v));
}

__global__ void maskbits_kernel(const int* __restrict__ mask) {
    int w = blockIdx.x * blockDim.x + threadIdx.x;
    const int4* src = (const int4*)mask + (size_t)w * 8;
    u32 bits = 0;
    #pragma unroll
    for (int i = 0; i < 8; ++i) {
        int4 v = src[i];
        bits |= (v.x != 0 ? 1u : 0u) << (i * 4);
        bits |= (v.y != 0 ? 1u : 0u) << (i * 4 + 1);
        bits |= (v.z != 0 ? 1u : 0u) << (i * 4 + 2);
        bits |= (v.w != 0 ? 1u : 0u) << (i * 4 + 3);
    }
    g_mbits[w] = bits;
}

__global__ void conv_k(const float* __restrict__ K) {
    size_t idx = (size_t)blockIdx.x * blockDim.x + threadIdx.x;
    float4 v = ((const float4*)K)[idx];
    u32 h0, l0, h1, l1;
    split2(v.x, v.y, h0, l0);
    split2(v.z, v.w, h1, l1);
    ((uint2*)g_khi)[idx] = make_uint2(h0, h1);
    ((uint2*)g_klo)[idx] = make_uint2(l0, l1);
}

__global__ void conv_v(const float* __restrict__ V) {
    __shared__ u32 hi[64 * 64], lo[64 * 64];
    const int kt = blockIdx.x, bh = blockIdx.y, tid = threadIdx.x;
    const float4* s4 = (const float4*)(V + ((size_t)bh * S_ + kt * 128) * D_);
    #pragma unroll
    for (int it = 0; it < 4; ++it) {
        int idx = it * THREADS + tid;
        int d4 = idx & 15, kp = idx >> 4;
        float4 a = s4[(2 * kp) * 16 + d4];
        float4 b = s4[(2 * kp + 1) * 16 + d4];
        float av[4] = {a.x, a.y, a.z, a.w};
        float bv[4] = {b.x, b.y, b.z, b.w};
        #pragma unroll
        for (int dd0 = 0; dd0 < 4; ++dd0) {
            int dd = (dd0 + d4) & 3;
            u32 h, l;
            split2(av[dd], bv[dd], h, l);
            hi[(4 * d4 + dd) * 64 + kp] = h;
            lo[(4 * d4 + dd) * 64 + kp] = l;
        }
    }
    __syncthreads();
    const size_t base = ((size_t)bh * NKT + kt) * 4096;
    uint4* gh = (uint4*)(g_vthi + base);
    uint4* gl = (uint4*)(g_vtlo + base);
    #pragma unroll
    for (int it = 0; it < 4; ++it) {
        int idx = it * THREADS + tid;
        gh[idx] = ((uint4*)hi)[idx];
        gl[idx] = ((uint4*)lo)[idx];
    }
}

__device__ __forceinline__ void stage_k_async(const u32* __restrict__ ghi,
                                              const u32* __restrict__ glo,
                                              u32 smhi, u32 smlo, int tid) {
    #pragma unroll
    for (int it = 0; it < 4; ++it) {
        int idx = it * THREADS + tid;
        int r = idx >> 3, c = idx & 7;
        u32 off = (u32)((r * KQ_STR + c * 4) * 4);
        cpa16(smhi + off, ghi + (size_t)idx * 4);
        cpa16(smlo + off, glo + (size_t)idx * 4);
    }
}
__device__ __forceinline__ void stage_v_async(const u32* __restrict__ ghi,
                                              const u32* __restrict__ glo,
                                              u32 smhi, u32 smlo, int tid) {
    #pragma unroll
    for (int it = 0; it < 4; ++it) {
        int idx = it * THREADS + tid;
        int r = idx >> 4, c = idx & 15;
        u32 off = (u32)((r * VT_STR + c * 4) * 4);
        cpa16(smhi + off, ghi + (size_t)idx * 4);
        cpa16(smlo + off, glo + (size_t)idx * 4);
    }
}

// ============ kernel 1: S=QK^T -> e=exp(masked) -> fp16 e-buffer + row sums ============
__global__ __launch_bounds__(THREADS, 2)
void attn_qk(const float* __restrict__ Q, int bh_base)
{
    extern __shared__ char sm[];

    const int tid = threadIdx.x, wid = tid >> 5, lane = tid & 31;
    const int g = lane >> 2, i = lane & 3;
    const int trow = lane & 7, tmat = lane >> 3;
    const int q0 = blockIdx.x * 128, bh = blockIdx.y + bh_base, b = bh >> 4;
    const int qw = wid * 16;

    const u32* KbH = g_khi + (size_t)bh * S_ * 32;
    const u32* KbL = g_klo + (size_t)bh * S_ * 32;

    u32 qh[4][4], ql[4][4];
    {
        const float* qa = Q + ((size_t)bh * S_ + q0 + qw + g) * D_;
        const float* qb = qa + 8 * D_;
        #pragma unroll
        for (int kc = 0; kc < 4; ++kc) {
            float2 a0 = *(const float2*)(qa + 16 * kc + 2 * i);
            float2 a1 = *(const float2*)(qa + 16 * kc + 8 + 2 * i);
            float2 b0 = *(const float2*)(qb + 16 * kc + 2 * i);
            float2 b1 = *(const float2*)(qb + 16 * kc + 8 + 2 * i);
            split2(a0.x * 0.125f, a0.y * 0.125f, qh[kc][0], ql[kc][0]);
            split2(b0.x * 0.125f, b0.y * 0.125f, qh[kc][1], ql[kc][1]);
            split2(a1.x * 0.125f, a1.y * 0.125f, qh[kc][2], ql[kc][2]);
            split2(b1.x * 0.125f, b1.y * 0.125f, qh[kc][3], ql[kc][3]);
        }
    }

    const u32* mra = g_mbits + (size_t)(b * S_ + q0 + qw + g) * (S_ / 32);
    const u32* mrb = mra + 8 * (S_ / 32);
    u32* ebA = g_ebuf + (size_t)(bh * S_ + q0 + qw + g) * (S_ / 2);
    u32* ebB = ebA + 8 * (S_ / 2);

    float sa = 0.f, sb = 0.f;

    const u32 smbase = smem_u32(sm);
    stage_k_async(KbH, KbL, smbase, smbase + KBUF, tid);
    CP_COMMIT();

    for (int kt = 0; kt < NKT; ++kt) {
        if (kt + 1 < NKT) {
            const u32 nb = smbase + ((kt + 1) & 1) * 2 * KBUF;
            stage_k_async(KbH + (size_t)(kt + 1) * 128 * 32,
                          KbL + (size_t)(kt + 1) * 128 * 32, nb, nb + KBUF, tid);
            CP_COMMIT();
            CP_WAIT1();
        } else {
            CP_WAIT0();
        }
        __syncthreads();

        const u32 khi_u = smbase + (kt & 1) * 2 * KBUF;
        const u32 klo_u = khi_u + KBUF;

        const uint4 wa4 = *(const uint4*)(mra + kt * 4);
        const uint4 wb4 = *(const uint4*)(mrb + kt * 4);
        const u32 waw[4] = {wa4.x, wa4.y, wa4.z, wa4.w};
        const u32 wbw[4] = {wb4.x, wb4.y, wb4.z, wb4.w};

        #pragma unroll
        for (int sub = 0; sub < 2; ++sub) {
            #pragma unroll
            for (int jq = 0; jq < 2; ++jq) {
                float c[4][4];
                #pragma unroll
                for (int j = 0; j < 4; ++j)
                    c[j][0] = c[j][1] = c[j][2] = c[j][3] = 0.f;

                #pragma unroll
                for (int j4 = 0; j4 < 4; ++j4) {
                    int nrow = sub * 64 + jq * 32 + j4 * 8 + trow;
                    u32 rb = (u32)((nrow * KQ_STR + tmat * 4) * 4);
                    u32 bhv[8], blv[8];
                    ldm4(&bhv[0], khi_u + rb);
                    ldm4(&bhv[4], khi_u + rb + 64);
                    ldm4(&blv[0], klo_u + rb);
                    ldm4(&blv[4], klo_u + rb + 64);
                    #pragma unroll
                    for (int kc = 0; kc < 4; ++kc) {
                        mma16816(c[j4], qh[kc], bhv[2 * kc], bhv[2 * kc + 1]);
                        mma16816(c[j4], qh[kc], blv[2 * kc], blv[2 * kc + 1]);
                        mma16816(c[j4], ql[kc], bhv[2 * kc], bhv[2 * kc + 1]);
                    }
                }

                u32 wa = waw[sub * 2 + jq];
                u32 wb = wbw[sub * 2 + jq];
                int ubase = kt * 64 + sub * 32 + jq * 16 + i;
                #pragma unroll
                for (int j4 = 0; j4 < 4; ++j4) {
                    int sh = j4 * 8 + 2 * i;
                    u32 ba = wa >> sh, bb = wb >> sh;
                    float e0 = (ba & 1u) ? __expf(c[j4][0]) : 0.f;
                    float e1 = (ba & 2u) ? __expf(c[j4][1]) : 0.f;
                    float e2 = (bb & 1u) ? __expf(c[j4][2]) : 0.f;
                    float e3 = (bb & 2u) ? __expf(c[j4][3]) : 0.f;
                    sa += e0 + e1;
                    sb += e2 + e3;
                    __stcs(&ebA[ubase + j4 * 4], pack_h2(e0, e1));
                    __stcs(&ebB[ubase + j4 * 4], pack_h2(e2, e3));
                }
            }
        }
        __syncthreads();
    }

    sa += __shfl_xor_sync(0xffffffffu, sa, 1);
    sa += __shfl_xor_sync(0xffffffffu, sa, 2);
    sb += __shfl_xor_sync(0xffffffffu, sb, 1);
    sb += __shfl_xor_sync(0xffffffffu, sb, 2);
    if (i == 0) {
        g_inv[(size_t)bh * S_ + q0 + qw + g]     = (sa > 0.f) ? (1.0f / sa) : 0.f;
        g_inv[(size_t)bh * S_ + q0 + qw + g + 8] = (sb > 0.f) ? (1.0f / sb) : 0.f;
    }
}

// ============ kernel 2: attn = e*inv (fp32) + (e @ V)*inv -> out ============
__global__ __launch_bounds__(THREADS, 2)
void attn_pv(float* __restrict__ outp, float* __restrict__ attn, int bh_base)
{
    extern __shared__ char sm[];

    const int tid = threadIdx.x, wid = tid >> 5, lane = tid & 31;
    const int g = lane >> 2, i = lane & 3;
    const int trow = lane & 7, tmat = lane >> 3;
    const int q0 = blockIdx.x * 128, bh = blockIdx.y + bh_base;
    const int qw = wid * 16;

    const u32* VbH = g_vthi + (size_t)bh * NKT * 4096;
    const u32* VbL = g_vtlo + (size_t)bh * NKT * 4096;
    const u32* ebA = g_ebuf + (size_t)(bh * S_ + q0 + qw + g) * (S_ / 2);
    const u32* ebB = ebA + 8 * (S_ / 2);

    float* arowA = nullptr; float* arowB = nullptr;
    if (attn) {
        arowA = attn + ((size_t)bh * S_ + q0 + qw + g) * S_;
        arowB = arowA + 8 * S_;
    }

    const float inva = __ldg(&g_inv[(size_t)bh * S_ + q0 + qw + g]);
    const float invb = __ldg(&g_inv[(size_t)bh * S_ + q0 + qw + g + 8]);

    float o[8][4];
    #pragma unroll
    for (int d = 0; d < 8; ++d) o[d][0] = o[d][1] = o[d][2] = o[d][3] = 0.f;

    const u32 smbase = smem_u32(sm);
    stage_v_async(VbH, VbL, smbase, smbase + VBUF, tid);
    CP_COMMIT();

    for (int kt = 0; kt < NKT; ++kt) {
        if (kt + 1 < NKT) {
            const u32 nb = smbase + ((kt + 1) & 1) * 2 * VBUF;
            stage_v_async(VbH + (size_t)(kt + 1) * 4096,
                          VbL + (size_t)(kt + 1) * 4096, nb, nb + VBUF, tid);
            CP_COMMIT();
            CP_WAIT1();
        } else {
            CP_WAIT0();
        }
        __syncthreads();

        const u32 vthi_u = smbase + (kt & 1) * 2 * VBUF;
        const u32 vtlo_u = vthi_u + VBUF;

        #pragma unroll
        for (int sub = 0; sub < 2; ++sub) {
            #pragma unroll
            for (int jq = 0; jq < 2; ++jq) {
                const int grp = kt * 64 + sub * 32 + jq * 16;

                u32 aa[2][4];
                #pragma unroll
                for (int kc2 = 0; kc2 < 2; ++kc2) {
                    aa[kc2][0] = __ldcs(&ebA[grp + kc2 * 8 + i]);
                    aa[kc2][1] = __ldcs(&ebB[grp + kc2 * 8 + i]);
                    aa[kc2][2] = __ldcs(&ebA[grp + kc2 * 8 + 4 + i]);
                    aa[kc2][3] = __ldcs(&ebB[grp + kc2 * 8 + 4 + i]);
                }

                if (arowA) {
                    int colbase = kt * 128 + sub * 64 + jq * 32 + 2 * i;
                    #pragma unroll
                    for (int kc2 = 0; kc2 < 2; ++kc2) {
                        float2 f0 = unpack_h2(aa[kc2][0]);
                        float2 f1 = unpack_h2(aa[kc2][1]);
                        float2 f2 = unpack_h2(aa[kc2][2]);
                        float2 f3 = unpack_h2(aa[kc2][3]);
                        __stcs((float2*)&arowA[colbase + kc2 * 16],
                               make_float2(f0.x * inva, f0.y * inva));
                        __stcs((float2*)&arowB[colbase + kc2 * 16],
                               make_float2(f1.x * invb, f1.y * invb));
                        __stcs((float2*)&arowA[colbase + kc2 * 16 + 8],
                               make_float2(f2.x * inva, f2.y * inva));
                        __stcs((float2*)&arowB[colbase + kc2 * 16 + 8],
                               make_float2(f3.x * invb, f3.y * invb));
                    }
                }

                #pragma unroll
                for (int dblk = 0; dblk < 8; ++dblk) {
                    u32 rb = (u32)(((dblk * 8 + trow) * VT_STR
                                    + sub * 32 + jq * 16 + tmat * 4) * 4);
                    u32 vh[4], vl[4];
                    ldm4(vh, vthi_u + rb);
                    ldm4(vl, vtlo_u + rb);
                    #pragma unroll
                    for (int kc2 = 0; kc2 < 2; ++kc2) {
                        mma16816(o[dblk], aa[kc2], vh[2 * kc2], vh[2 * kc2 + 1]);
                        mma16816(o[dblk], aa[kc2], vl[2 * kc2], vl[2 * kc2 + 1]);
                    }
                }
            }
        }
        __syncthreads();
    }

    if (outp) {
        float* orowA = outp + ((size_t)bh * S_ + q0 + qw + g) * D_ + 2 * i;
        float* orowB = orowA + 8 * D_;
        #pragma unroll
        for (int dblk = 0; dblk < 8; ++dblk) {
            *(float2*)&orowA[dblk * 8] = make_float2(o[dblk][0] * inva, o[dblk][1] * inva);
            *(float2*)&orowB[dblk * 8] = make_float2(o[dblk][2] * invb, o[dblk][3] * invb);
        }
    }
}

extern "C" void kernel_launch(void* const* d_in, const int* in_sizes, int n_in,
                              void* d_out, int out_size)
{
    const float* Q    = (const float*)d_in[0];
    const float* K    = (const float*)d_in[1];
    const float* V    = (const float*)d_in[2];
    const int*   mask = (const int*)d_in[3];

    const size_t OUT_E  = (size_t)B_ * H_ * S_ * D_;
    const size_t ATTN_E = (size_t)B_ * H_ * S_ * S_;
    float* o = nullptr; float* a = nullptr;
    if ((size_t)out_size >= OUT_E + ATTN_E) { o = (float*)d_out; a = (float*)d_out + OUT_E; }
    else if ((size_t)out_size == ATTN_E)    { a = (float*)d_out; }
    else                                    { o = (float*)d_out; }

    maskbits_kernel<<<(B_ * S_ * (S_ / 32)) / 256, 256>>>(mask);
    conv_k<<<(B_ * H_ * S_ * (D_ / 4)) / 256, 256>>>(K);
    conv_v<<<dim3(NKT, B_ * H_), 256>>>(V);

    cudaFuncSetAttribute(attn_qk, cudaFuncAttributeMaxDynamicSharedMemorySize, SMEM_K);
    cudaFuncSetAttribute(attn_pv, cudaFuncAttributeMaxDynamicSharedMemorySize, SMEM_V);

    // fork pv onto a second stream, chunked by bh, overlapping with later qk chunks
    cudaStream_t s2;
    cudaStreamCreateWithFlags(&s2, cudaStreamNonBlocking);

    const int NCH = 4, CH = (B_ * H_) / NCH;      // 4 chunks x 16 bh
    cudaEvent_t ev[NCH], evj;
    for (int c = 0; c < NCH; ++c) {
        attn_qk<<<dim3(S_ / 128, CH), THREADS, SMEM_K>>>(Q, c * CH);
        cudaEventCreateWithFlags(&ev[c], cudaEventDisableTiming);
        cudaEventRecord(ev[c], 0);
    }
    for (int c = 0; c < NCH; ++c) {
        cudaStreamWaitEvent(s2, ev[c], 0);
        attn_pv<<<dim3(S_ / 128, CH), THREADS, SMEM_V, s2>>>(o, a, c * CH);
    }
    cudaEventCreateWithFlags(&evj, cudaEventDisableTiming);
    cudaEventRecord(evj, s2);
    cudaStreamWaitEvent((cudaStream_t)0, evj, 0);
}

// round 13
// speedup vs baseline: 1.1614x; 1.1614x over previous
#include <cuda_runtime.h>
#include <cuda_fp16.h>

typedef unsigned int u32;

#define B_ 4
#define H_ 16
#define S_ 2048
#define D_ 64
#define NKT 16
#define THREADS 256
#define KQ_STR 36      // u32 per K smem row (144B stride; conflict-free ldmatrix)
#define VT_STR 68      // u32 per Vt smem row (272B stride; conflict-free ldmatrix)

__device__ u32   g_mbits[(size_t)B_ * S_ * (S_ / 32)];     // 2 MB mask bitfield
__device__ float g_inv[(size_t)B_ * H_ * S_];              // per-row 1/sum
__device__ u32   g_ebuf[(size_t)B_ * H_ * S_ * (S_ / 2)];  // 0.54 GB fp16x2 e-buffer
// pre-converted operands (hi plane only), tile-major
__device__ u32   g_khi[(size_t)B_ * H_ * S_ * 32];         // [bh][s][32 u32]
__device__ u32   g_vthi[(size_t)B_ * H_ * NKT * 4096];     // [bh][kt][64 d][64 kp]

#define KBUF   (128 * KQ_STR * 4)                          // 18432 B
#define SMEM_K (2 * KBUF)                                  // 36864 B (double buffer, hi only)
#define VBUF   (64 * VT_STR * 4)                           // 17408 B
#define SMEM_V (2 * VBUF)                                  // 34816 B

__device__ __forceinline__ void mma16816(float c[4], const u32 a[4], u32 b0, u32 b1) {
    asm volatile("mma.sync.aligned.m16n8k16.row.col.f32.f16.f16.f32 "
                 "{%0,%1,%2,%3}, {%4,%5,%6,%7}, {%8,%9}, {%0,%1,%2,%3};"
                 : "+f"(c[0]), "+f"(c[1]), "+f"(c[2]), "+f"(c[3])
                 : "r"(a[0]), "r"(a[1]), "r"(a[2]), "r"(a[3]), "r"(b0), "r"(b1));
}

__device__ __forceinline__ void ldm4(u32* r, u32 addr) {
    asm volatile("ldmatrix.sync.aligned.m8n8.x4.shared.b16 {%0,%1,%2,%3}, [%4];"
                 : "=r"(r[0]), "=r"(r[1]), "=r"(r[2]), "=r"(r[3]) : "r"(addr));
}

__device__ __forceinline__ u32 smem_u32(const void* p) {
    return (u32)__cvta_generic_to_shared(p);
}

__device__ __forceinline__ void cpa16(u32 dst, const void* src) {
    asm volatile("cp.async.cg.shared.global [%0], [%1], 16;" :: "r"(dst), "l"(src));
}
#define CP_COMMIT() asm volatile("cp.async.commit_group;" ::: "memory")
#define CP_WAIT1()  asm volatile("cp.async.wait_group 1;" ::: "memory")
#define CP_WAIT0()  asm volatile("cp.async.wait_group 0;" ::: "memory")

__device__ __forceinline__ void split2(float x, float y, u32& h, u32& l) {
    __half2 H = __floats2half2_rn(x, y);
    h = *reinterpret_cast<u32*>(&H);
    float2 f = __half22float2(H);
    __half2 L = __floats2half2_rn(x - f.x, y - f.y);
    l = *reinterpret_cast<u32*>(&L);
}
__device__ __forceinline__ u32 pack_h2(float x, float y) {
    __half2 H = __floats2half2_rn(x, y);
    return *reinterpret_cast<u32*>(&H);
}
__device__ __forceinline__ float2 unpack_h2(u32 v) {
    return __half22float2(*reinterpret_cast<__half2*>(&v));
}

__global__ void maskbits_kernel(const int* __restrict__ mask) {
    int w = blockIdx.x * blockDim.x + threadIdx.x;
    const int4* src = (const int4*)mask + (size_t)w * 8;
    u32 bits = 0;
    #pragma unroll
    for (int i = 0; i < 8; ++i) {
        int4 v = src[i];
        bits |= (v.x != 0 ? 1u : 0u) << (i * 4);
        bits |= (v.y != 0 ? 1u : 0u) << (i * 4 + 1);
        bits |= (v.z != 0 ? 1u : 0u) << (i * 4 + 2);
        bits |= (v.w != 0 ? 1u : 0u) << (i * 4 + 3);
    }
    g_mbits[w] = bits;
}

// ---- pre-convert K (hi only): fp32 [bh][s][64] -> u32 plane [bh][s][32] ----
__global__ void conv_k(const float* __restrict__ K) {
    size_t idx = (size_t)blockIdx.x * blockDim.x + threadIdx.x;
    float4 v = ((const float4*)K)[idx];
    ((uint2*)g_khi)[idx] = make_uint2(pack_h2(v.x, v.y), pack_h2(v.z, v.w));
}

// ---- pre-convert + transpose V (hi only): fp32 [bh][k][64] -> Vt [bh][kt][64][64] ----
__global__ void conv_v(const float* __restrict__ V) {
    __shared__ u32 hi[64 * 64];
    const int kt = blockIdx.x, bh = blockIdx.y, tid = threadIdx.x;
    const float4* s4 = (const float4*)(V + ((size_t)bh * S_ + kt * 128) * D_);
    #pragma unroll
    for (int it = 0; it < 4; ++it) {
        int idx = it * THREADS + tid;
        int d4 = idx & 15, kp = idx >> 4;
        float4 a = s4[(2 * kp) * 16 + d4];
        float4 b = s4[(2 * kp + 1) * 16 + d4];
        float av[4] = {a.x, a.y, a.z, a.w};
        float bv[4] = {b.x, b.y, b.z, b.w};
        #pragma unroll
        for (int dd0 = 0; dd0 < 4; ++dd0) {
            int dd = (dd0 + d4) & 3;
            hi[(4 * d4 + dd) * 64 + kp] = pack_h2(av[dd], bv[dd]);
        }
    }
    __syncthreads();
    uint4* gh = (uint4*)(g_vthi + ((size_t)bh * NKT + kt) * 4096);
    #pragma unroll
    for (int it = 0; it < 4; ++it) {
        int idx = it * THREADS + tid;
        gh[idx] = ((uint4*)hi)[idx];
    }
}

// ---- cp.async staging, single plane ----
__device__ __forceinline__ void stage_k_async(const u32* __restrict__ ghi, u32 smhi, int tid) {
    #pragma unroll
    for (int it = 0; it < 4; ++it) {
        int idx = it * THREADS + tid;          // 0..1023 16B chunks
        int r = idx >> 3, c = idx & 7;
        cpa16(smhi + (u32)((r * KQ_STR + c * 4) * 4), ghi + (size_t)idx * 4);
    }
}
__device__ __forceinline__ void stage_v_async(const u32* __restrict__ ghi, u32 smhi, int tid) {
    #pragma unroll
    for (int it = 0; it < 4; ++it) {
        int idx = it * THREADS + tid;
        int r = idx >> 4, c = idx & 15;
        cpa16(smhi + (u32)((r * VT_STR + c * 4) * 4), ghi + (size_t)idx * 4);
    }
}

// ============ kernel 1: S=QK^T (Qhi*Khi + Qlo*Khi) -> e -> fp16 e-buffer + sums ============
__global__ __launch_bounds__(THREADS, 2)
void attn_qk(const float* __restrict__ Q)
{
    extern __shared__ char sm[];

    const int tid = threadIdx.x, wid = tid >> 5, lane = tid & 31;
    const int g = lane >> 2, i = lane & 3;
    const int trow = lane & 7, tmat = lane >> 3;
    const int q0 = blockIdx.x * 128, bh = blockIdx.y, b = bh >> 4;
    const int qw = wid * 16;

    const u32* KbH = g_khi + (size_t)bh * S_ * 32;

    u32 qh[4][4], ql[4][4];
    {
        const float* qa = Q + ((size_t)bh * S_ + q0 + qw + g) * D_;
        const float* qb = qa + 8 * D_;
        #pragma unroll
        for (int kc = 0; kc < 4; ++kc) {
            float2 a0 = *(const float2*)(qa + 16 * kc + 2 * i);
            float2 a1 = *(const float2*)(qa + 16 * kc + 8 + 2 * i);
            float2 b0 = *(const float2*)(qb + 16 * kc + 2 * i);
            float2 b1 = *(const float2*)(qb + 16 * kc + 8 + 2 * i);
            split2(a0.x * 0.125f, a0.y * 0.125f, qh[kc][0], ql[kc][0]);
            split2(b0.x * 0.125f, b0.y * 0.125f, qh[kc][1], ql[kc][1]);
            split2(a1.x * 0.125f, a1.y * 0.125f, qh[kc][2], ql[kc][2]);
            split2(b1.x * 0.125f, b1.y * 0.125f, qh[kc][3], ql[kc][3]);
        }
    }

    const u32* mra = g_mbits + (size_t)(b * S_ + q0 + qw + g) * (S_ / 32);
    const u32* mrb = mra + 8 * (S_ / 32);
    u32* ebA = g_ebuf + (size_t)(bh * S_ + q0 + qw + g) * (S_ / 2);
    u32* ebB = ebA + 8 * (S_ / 2);

    float sa = 0.f, sb = 0.f;

    const u32 smbase = smem_u32(sm);
    stage_k_async(KbH, smbase, tid);
    CP_COMMIT();

    for (int kt = 0; kt < NKT; ++kt) {
        if (kt + 1 < NKT) {
            stage_k_async(KbH + (size_t)(kt + 1) * 128 * 32,
                          smbase + ((kt + 1) & 1) * KBUF, tid);
            CP_COMMIT();
            CP_WAIT1();
        } else {
            CP_WAIT0();
        }
        __syncthreads();

        const u32 khi_u = smbase + (kt & 1) * KBUF;

        const uint4 wa4 = *(const uint4*)(mra + kt * 4);
        const uint4 wb4 = *(const uint4*)(mrb + kt * 4);
        const u32 waw[4] = {wa4.x, wa4.y, wa4.z, wa4.w};
        const u32 wbw[4] = {wb4.x, wb4.y, wb4.z, wb4.w};

        #pragma unroll
        for (int sub = 0; sub < 2; ++sub) {
            #pragma unroll
            for (int jq = 0; jq < 2; ++jq) {
                float c[4][4];
                #pragma unroll
                for (int j = 0; j < 4; ++j)
                    c[j][0] = c[j][1] = c[j][2] = c[j][3] = 0.f;

                #pragma unroll
                for (int j4 = 0; j4 < 4; ++j4) {
                    int nrow = sub * 64 + jq * 32 + j4 * 8 + trow;
                    u32 rb = (u32)((nrow * KQ_STR + tmat * 4) * 4);
                    u32 bhv[8];
                    ldm4(&bhv[0], khi_u + rb);
                    ldm4(&bhv[4], khi_u + rb + 64);
                    #pragma unroll
                    for (int kc = 0; kc < 4; ++kc) {
                        mma16816(c[j4], qh[kc], bhv[2 * kc], bhv[2 * kc + 1]);
                        mma16816(c[j4], ql[kc], bhv[2 * kc], bhv[2 * kc + 1]);
                    }
                }

                u32 wa = waw[sub * 2 + jq];
                u32 wb = wbw[sub * 2 + jq];
                int ubase = kt * 64 + sub * 32 + jq * 16 + i;
                #pragma unroll
                for (int j4 = 0; j4 < 4; ++j4) {
                    int sh = j4 * 8 + 2 * i;
                    u32 ba = wa >> sh, bb = wb >> sh;
                    float e0 = (ba & 1u) ? __expf(c[j4][0]) : 0.f;
                    float e1 = (ba & 2u) ? __expf(c[j4][1]) : 0.f;
                    float e2 = (bb & 1u) ? __expf(c[j4][2]) : 0.f;
                    float e3 = (bb & 2u) ? __expf(c[j4][3]) : 0.f;
                    sa += e0 + e1;
                    sb += e2 + e3;
                    __stcs(&ebA[ubase + j4 * 4], pack_h2(e0, e1));
                    __stcs(&ebB[ubase + j4 * 4], pack_h2(e2, e3));
                }
            }
        }
        __syncthreads();
    }

    sa += __shfl_xor_sync(0xffffffffu, sa, 1);
    sa += __shfl_xor_sync(0xffffffffu, sa, 2);
    sb += __shfl_xor_sync(0xffffffffu, sb, 1);
    sb += __shfl_xor_sync(0xffffffffu, sb, 2);
    if (i == 0) {
        g_inv[(size_t)bh * S_ + q0 + qw + g]     = (sa > 0.f) ? (1.0f / sa) : 0.f;
        g_inv[(size_t)bh * S_ + q0 + qw + g + 8] = (sb > 0.f) ? (1.0f / sb) : 0.f;
    }
}

// ============ kernel 2: attn = e*inv (fp32) + (e @ Vhi)*inv -> out ============
__global__ __launch_bounds__(THREADS, 2)
void attn_pv(float* __restrict__ outp, float* __restrict__ attn)
{
    extern __shared__ char sm[];

    const int tid = threadIdx.x, wid = tid >> 5, lane = tid & 31;
    const int g = lane >> 2, i = lane & 3;
    const int trow = lane & 7, tmat = lane >> 3;
    const int q0 = blockIdx.x * 128, bh = blockIdx.y;
    const int qw = wid * 16;

    const u32* VbH = g_vthi + (size_t)bh * NKT * 4096;
    const u32* ebA = g_ebuf + (size_t)(bh * S_ + q0 + qw + g) * (S_ / 2);
    const u32* ebB = ebA + 8 * (S_ / 2);

    float* arowA = nullptr; float* arowB = nullptr;
    if (attn) {
        arowA = attn + ((size_t)bh * S_ + q0 + qw + g) * S_;
        arowB = arowA + 8 * S_;
    }

    const float inva = __ldg(&g_inv[(size_t)bh * S_ + q0 + qw + g]);
    const float invb = __ldg(&g_inv[(size_t)bh * S_ + q0 + qw + g + 8]);

    float o[8][4];
    #pragma unroll
    for (int d = 0; d < 8; ++d) o[d][0] = o[d][1] = o[d][2] = o[d][3] = 0.f;

    const u32 smbase = smem_u32(sm);
    stage_v_async(VbH, smbase, tid);
    CP_COMMIT();

    for (int kt = 0; kt < NKT; ++kt) {
        if (kt + 1 < NKT) {
            stage_v_async(VbH + (size_t)(kt + 1) * 4096,
                          smbase + ((kt + 1) & 1) * VBUF, tid);
            CP_COMMIT();
            CP_WAIT1();
        } else {
            CP_WAIT0();
        }
        __syncthreads();

        const u32 vthi_u = smbase + (kt & 1) * VBUF;

        #pragma unroll
        for (int sub = 0; sub < 2; ++sub) {
            #pragma unroll
            for (int jq = 0; jq < 2; ++jq) {
                const int grp = kt * 64 + sub * 32 + jq * 16;

                u32 aa[2][4];
                #pragma unroll
                for (int kc2 = 0; kc2 < 2; ++kc2) {
                    aa[kc2][0] = __ldcs(&ebA[grp + kc2 * 8 + i]);
                    aa[kc2][1] = __ldcs(&ebB[grp + kc2 * 8 + i]);
                    aa[kc2][2] = __ldcs(&ebA[grp + kc2 * 8 + 4 + i]);
                    aa[kc2][3] = __ldcs(&ebB[grp + kc2 * 8 + 4 + i]);
                }

                if (arowA) {
                    int colbase = kt * 128 + sub * 64 + jq * 32 + 2 * i;
                    #pragma unroll
                    for (int kc2 = 0; kc2 < 2; ++kc2) {
                        float2 f0 = unpack_h2(aa[kc2][0]);
                        float2 f1 = unpack_h2(aa[kc2][1]);
                        float2 f2 = unpack_h2(aa[kc2][2]);
                        float2 f3 = unpack_h2(aa[kc2][3]);
                        __stcs((float2*)&arowA[colbase + kc2 * 16],
                               make_float2(f0.x * inva, f0.y * inva));
                        __stcs((float2*)&arowB[colbase + kc2 * 16],
                               make_float2(f1.x * invb, f1.y * invb));
                        __stcs((float2*)&arowA[colbase + kc2 * 16 + 8],
                               make_float2(f2.x * inva, f2.y * inva));
                        __stcs((float2*)&arowB[colbase + kc2 * 16 + 8],
                               make_float2(f3.x * invb, f3.y * invb));
                    }
                }

                #pragma unroll
                for (int dblk = 0; dblk < 8; ++dblk) {
                    u32 rb = (u32)(((dblk * 8 + trow) * VT_STR
                                    + sub * 32 + jq * 16 + tmat * 4) * 4);
                    u32 vh[4];
                    ldm4(vh, vthi_u + rb);
                    #pragma unroll
                    for (int kc2 = 0; kc2 < 2; ++kc2)
                        mma16816(o[dblk], aa[kc2], vh[2 * kc2], vh[2 * kc2 + 1]);
                }
            }
        }
        __syncthreads();
    }

    if (outp) {
        float* orowA = outp + ((size_t)bh * S_ + q0 + qw + g) * D_ + 2 * i;
        float* orowB = orowA + 8 * D_;
        #pragma unroll
        for (int dblk = 0; dblk < 8; ++dblk) {
            *(float2*)&orowA[dblk * 8] = make_float2(o[dblk][0] * inva, o[dblk][1] * inva);
            *(float2*)&orowB[dblk * 8] = make_float2(o[dblk][2] * invb, o[dblk][3] * invb);
        }
    }
}

extern "C" void kernel_launch(void* const* d_in, const int* in_sizes, int n_in,
                              void* d_out, int out_size)
{
    const float* Q    = (const float*)d_in[0];
    const float* K    = (const float*)d_in[1];
    const float* V    = (const float*)d_in[2];
    const int*   mask = (const int*)d_in[3];

    const size_t OUT_E  = (size_t)B_ * H_ * S_ * D_;
    const size_t ATTN_E = (size_t)B_ * H_ * S_ * S_;
    float* o = nullptr; float* a = nullptr;
    if ((size_t)out_size >= OUT_E + ATTN_E) { o = (float*)d_out; a = (float*)d_out + OUT_E; }
    else if ((size_t)out_size == ATTN_E)    { a = (float*)d_out; }
    else                                    { o = (float*)d_out; }

    maskbits_kernel<<<(B_ * S_ * (S_ / 32)) / 256, 256>>>(mask);
    conv_k<<<(B_ * H_ * S_ * (D_ / 4)) / 256, 256>>>(K);
    conv_v<<<dim3(NKT, B_ * H_), 256>>>(V);

    cudaFuncSetAttribute(attn_qk, cudaFuncAttributeMaxDynamicSharedMemorySize, SMEM_K);
    cudaFuncSetAttribute(attn_pv, cudaFuncAttributeMaxDynamicSharedMemorySize, SMEM_V);

    dim3 grid(S_ / 128, B_ * H_);
    attn_qk<<<grid, THREADS, SMEM_K>>>(Q);
    attn_pv<<<grid, THREADS, SMEM_V>>>(o, a);
}

// round 14
// speedup vs baseline: 1.4473x; 1.2462x over previous
#include <cuda_runtime.h>
#include <cuda_fp16.h>

typedef unsigned int u32;

#define B_ 4
#define H_ 16
#define S_ 2048
#define D_ 64
#define NKT 16
#define THREADS 256
#define KQ_STR 36      // u32 per K smem row (144B stride; conflict-free ldmatrix)
#define VT_STR 68      // u32 per Vt smem row (272B stride; conflict-free ldmatrix)

__device__ u32   g_mbits[(size_t)B_ * S_ * (S_ / 32)];     // 2 MB mask bitfield
__device__ float g_inv[(size_t)B_ * H_ * S_];              // per-row 1/sum
__device__ u32   g_ebuf[(size_t)B_ * H_ * S_ * (S_ / 2)];  // 0.54 GB fp16x2 e-buffer
// pre-converted operands (hi plane only), tile-major
__device__ u32   g_khi[(size_t)B_ * H_ * S_ * 32];         // [bh][s][32 u32]
__device__ u32   g_vthi[(size_t)B_ * H_ * NKT * 4096];     // [bh][kt][64 d][64 kp]

#define KBUF   (128 * KQ_STR * 4)                          // 18432 B
#define VBUF   (64 * VT_STR * 4)                           // 17408 B
#define SMEM_F (2 * KBUF + 2 * VBUF)                       // 71680 B -> 2 CTAs/SM
#define VOFF   (2 * KBUF)

#define QSCALE 0.1803368801f                               // 0.125 * log2(e)

__device__ __forceinline__ void mma16816(float c[4], const u32 a[4], u32 b0, u32 b1) {
    asm volatile("mma.sync.aligned.m16n8k16.row.col.f32.f16.f16.f32 "
                 "{%0,%1,%2,%3}, {%4,%5,%6,%7}, {%8,%9}, {%0,%1,%2,%3};"
                 : "+f"(c[0]), "+f"(c[1]), "+f"(c[2]), "+f"(c[3])
                 : "r"(a[0]), "r"(a[1]), "r"(a[2]), "r"(a[3]), "r"(b0), "r"(b1));
}

__device__ __forceinline__ void ldm4(u32* r, u32 addr) {
    asm volatile("ldmatrix.sync.aligned.m8n8.x4.shared.b16 {%0,%1,%2,%3}, [%4];"
                 : "=r"(r[0]), "=r"(r[1]), "=r"(r[2]), "=r"(r[3]) : "r"(addr));
}

__device__ __forceinline__ u32 smem_u32(const void* p) {
    return (u32)__cvta_generic_to_shared(p);
}

__device__ __forceinline__ void cpa16(u32 dst, const void* src) {
    asm volatile("cp.async.cg.shared.global [%0], [%1], 16;" :: "r"(dst), "l"(src));
}
#define CP_COMMIT() asm volatile("cp.async.commit_group;" ::: "memory")
#define CP_WAIT1()  asm volatile("cp.async.wait_group 1;" ::: "memory")
#define CP_WAIT0()  asm volatile("cp.async.wait_group 0;" ::: "memory")

__device__ __forceinline__ void split2(float x, float y, u32& h, u32& l) {
    __half2 H = __floats2half2_rn(x, y);
    h = *reinterpret_cast<u32*>(&H);
    float2 f = __half22float2(H);
    __half2 L = __floats2half2_rn(x - f.x, y - f.y);
    l = *reinterpret_cast<u32*>(&L);
}
__device__ __forceinline__ u32 pack_h2(float x, float y) {
    __half2 H = __floats2half2_rn(x, y);
    return *reinterpret_cast<u32*>(&H);
}
__device__ __forceinline__ float2 unpack_h2(u32 v) {
    return __half22float2(*reinterpret_cast<__half2*>(&v));
}

__global__ void maskbits_kernel(const int* __restrict__ mask) {
    int w = blockIdx.x * blockDim.x + threadIdx.x;
    const int4* src = (const int4*)mask + (size_t)w * 8;
    u32 bits = 0;
    #pragma unroll
    for (int i = 0; i < 8; ++i) {
        int4 v = src[i];
        bits |= (v.x != 0 ? 1u : 0u) << (i * 4);
        bits |= (v.y != 0 ? 1u : 0u) << (i * 4 + 1);
        bits |= (v.z != 0 ? 1u : 0u) << (i * 4 + 2);
        bits |= (v.w != 0 ? 1u : 0u) << (i * 4 + 3);
    }
    g_mbits[w] = bits;
}

__global__ void conv_k(const float* __restrict__ K) {
    size_t idx = (size_t)blockIdx.x * blockDim.x + threadIdx.x;
    float4 v = ((const float4*)K)[idx];
    ((uint2*)g_khi)[idx] = make_uint2(pack_h2(v.x, v.y), pack_h2(v.z, v.w));
}

__global__ void conv_v(const float* __restrict__ V) {
    __shared__ u32 hi[64 * 64];
    const int kt = blockIdx.x, bh = blockIdx.y, tid = threadIdx.x;
    const float4* s4 = (const float4*)(V + ((size_t)bh * S_ + kt * 128) * D_);
    #pragma unroll
    for (int it = 0; it < 4; ++it) {
        int idx = it * THREADS + tid;
        int d4 = idx & 15, kp = idx >> 4;
        float4 a = s4[(2 * kp) * 16 + d4];
        float4 b = s4[(2 * kp + 1) * 16 + d4];
        float av[4] = {a.x, a.y, a.z, a.w};
        float bv[4] = {b.x, b.y, b.z, b.w};
        #pragma unroll
        for (int dd0 = 0; dd0 < 4; ++dd0) {
            int dd = (dd0 + d4) & 3;
            hi[(4 * d4 + dd) * 64 + kp] = pack_h2(av[dd], bv[dd]);
        }
    }
    __syncthreads();
    uint4* gh = (uint4*)(g_vthi + ((size_t)bh * NKT + kt) * 4096);
    #pragma unroll
    for (int it = 0; it < 4; ++it) {
        int idx = it * THREADS + tid;
        gh[idx] = ((uint4*)hi)[idx];
    }
}

__device__ __forceinline__ void stage_k_async(const u32* __restrict__ ghi, u32 smhi, int tid) {
    #pragma unroll
    for (int it = 0; it < 4; ++it) {
        int idx = it * THREADS + tid;
        int r = idx >> 3, c = idx & 7;
        cpa16(smhi + (u32)((r * KQ_STR + c * 4) * 4), ghi + (size_t)idx * 4);
    }
}
__device__ __forceinline__ void stage_v_async(const u32* __restrict__ ghi, u32 smhi, int tid) {
    #pragma unroll
    for (int it = 0; it < 4; ++it) {
        int idx = it * THREADS + tid;
        int r = idx >> 4, c = idx & 15;
        cpa16(smhi + (u32)((r * VT_STR + c * 4) * 4), ghi + (size_t)idx * 4);
    }
}

// ============ fused kernel: QK -> e (regs) -> {e-buffer store, PV mma} + out ============
__global__ __launch_bounds__(THREADS, 2)
void attn_fused(const float* __restrict__ Q, float* __restrict__ outp)
{
    extern __shared__ char sm[];

    const int tid = threadIdx.x, wid = tid >> 5, lane = tid & 31;
    const int g = lane >> 2, i = lane & 3;
    const int trow = lane & 7, tmat = lane >> 3;
    const int q0 = blockIdx.x * 128, bh = blockIdx.y, b = bh >> 4;
    const int qw = wid * 16;

    const u32* KbH = g_khi + (size_t)bh * S_ * 32;
    const u32* VbH = g_vthi + (size_t)bh * NKT * 4096;

    // Q fragments from gmem, scale*log2e folded (scores in log2 domain)
    u32 qh[4][4], ql[4][4];
    {
        const float* qa = Q + ((size_t)bh * S_ + q0 + qw + g) * D_;
        const float* qb = qa + 8 * D_;
        #pragma unroll
        for (int kc = 0; kc < 4; ++kc) {
            float2 a0 = *(const float2*)(qa + 16 * kc + 2 * i);
            float2 a1 = *(const float2*)(qa + 16 * kc + 8 + 2 * i);
            float2 b0 = *(const float2*)(qb + 16 * kc + 2 * i);
            float2 b1 = *(const float2*)(qb + 16 * kc + 8 + 2 * i);
            split2(a0.x * QSCALE, a0.y * QSCALE, qh[kc][0], ql[kc][0]);
            split2(b0.x * QSCALE, b0.y * QSCALE, qh[kc][1], ql[kc][1]);
            split2(a1.x * QSCALE, a1.y * QSCALE, qh[kc][2], ql[kc][2]);
            split2(b1.x * QSCALE, b1.y * QSCALE, qh[kc][3], ql[kc][3]);
        }
    }

    const u32* mra = g_mbits + (size_t)(b * S_ + q0 + qw + g) * (S_ / 32);
    const u32* mrb = mra + 8 * (S_ / 32);
    u32* ebA = g_ebuf + (size_t)(bh * S_ + q0 + qw + g) * (S_ / 2);
    u32* ebB = ebA + 8 * (S_ / 2);

    float sa = 0.f, sb = 0.f;
    float o[8][4];
    #pragma unroll
    for (int d = 0; d < 8; ++d) o[d][0] = o[d][1] = o[d][2] = o[d][3] = 0.f;

    const u32 smbase = smem_u32(sm);
    stage_k_async(KbH, smbase, tid);
    stage_v_async(VbH, smbase + VOFF, tid);
    CP_COMMIT();

    for (int kt = 0; kt < NKT; ++kt) {
        if (kt + 1 < NKT) {
            stage_k_async(KbH + (size_t)(kt + 1) * 128 * 32,
                          smbase + ((kt + 1) & 1) * KBUF, tid);
            stage_v_async(VbH + (size_t)(kt + 1) * 4096,
                          smbase + VOFF + ((kt + 1) & 1) * VBUF, tid);
            CP_COMMIT();
            CP_WAIT1();
        } else {
            CP_WAIT0();
        }
        __syncthreads();

        const u32 khi_u  = smbase + (kt & 1) * KBUF;
        const u32 vthi_u = smbase + VOFF + (kt & 1) * VBUF;

        const uint4 wa4 = *(const uint4*)(mra + kt * 4);
        const uint4 wb4 = *(const uint4*)(mrb + kt * 4);
        const u32 waw[4] = {wa4.x, wa4.y, wa4.z, wa4.w};
        const u32 wbw[4] = {wb4.x, wb4.y, wb4.z, wb4.w};

        #pragma unroll
        for (int sub = 0; sub < 2; ++sub) {
            #pragma unroll
            for (int jq = 0; jq < 2; ++jq) {
                float c[4][4];
                #pragma unroll
                for (int j = 0; j < 4; ++j)
                    c[j][0] = c[j][1] = c[j][2] = c[j][3] = 0.f;

                // ---- QK MMAs ----
                #pragma unroll
                for (int j4 = 0; j4 < 4; ++j4) {
                    int nrow = sub * 64 + jq * 32 + j4 * 8 + trow;
                    u32 rb = (u32)((nrow * KQ_STR + tmat * 4) * 4);
                    u32 bhv[8];
                    ldm4(&bhv[0], khi_u + rb);
                    ldm4(&bhv[4], khi_u + rb + 64);
                    #pragma unroll
                    for (int kc = 0; kc < 4; ++kc) {
                        mma16816(c[j4], qh[kc], bhv[2 * kc], bhv[2 * kc + 1]);
                        mma16816(c[j4], ql[kc], bhv[2 * kc], bhv[2 * kc + 1]);
                    }
                }

                // ---- mask + exp2 (scores already in log2 domain) ----
                u32 wa = waw[sub * 2 + jq];
                u32 wb = wbw[sub * 2 + jq];
                #pragma unroll
                for (int j4 = 0; j4 < 4; ++j4) {
                    int sh = j4 * 8 + 2 * i;
                    u32 ba = wa >> sh, bb = wb >> sh;
                    float e0 = (ba & 1u) ? exp2f(c[j4][0]) : 0.f;
                    float e1 = (ba & 2u) ? exp2f(c[j4][1]) : 0.f;
                    float e2 = (bb & 1u) ? exp2f(c[j4][2]) : 0.f;
                    float e3 = (bb & 2u) ? exp2f(c[j4][3]) : 0.f;
                    sa += e0 + e1;
                    sb += e2 + e3;
                    c[j4][0] = e0; c[j4][1] = e1; c[j4][2] = e2; c[j4][3] = e3;
                }

                // ---- pack e fragments; store to e-buffer; PV mma from regs ----
                const int grp = kt * 64 + sub * 32 + jq * 16;
                u32 aa[2][4];
                #pragma unroll
                for (int kc2 = 0; kc2 < 2; ++kc2) {
                    aa[kc2][0] = pack_h2(c[2 * kc2][0],     c[2 * kc2][1]);
                    aa[kc2][1] = pack_h2(c[2 * kc2][2],     c[2 * kc2][3]);
                    aa[kc2][2] = pack_h2(c[2 * kc2 + 1][0], c[2 * kc2 + 1][1]);
                    aa[kc2][3] = pack_h2(c[2 * kc2 + 1][2], c[2 * kc2 + 1][3]);
                    __stcs(&ebA[grp + kc2 * 8 + i],     aa[kc2][0]);
                    __stcs(&ebB[grp + kc2 * 8 + i],     aa[kc2][1]);
                    __stcs(&ebA[grp + kc2 * 8 + 4 + i], aa[kc2][2]);
                    __stcs(&ebB[grp + kc2 * 8 + 4 + i], aa[kc2][3]);
                }

                #pragma unroll
                for (int dblk = 0; dblk < 8; ++dblk) {
                    u32 rb = (u32)(((dblk * 8 + trow) * VT_STR
                                    + sub * 32 + jq * 16 + tmat * 4) * 4);
                    u32 vh[4];
                    ldm4(vh, vthi_u + rb);
                    #pragma unroll
                    for (int kc2 = 0; kc2 < 2; ++kc2)
                        mma16816(o[dblk], aa[kc2], vh[2 * kc2], vh[2 * kc2 + 1]);
                }
            }
        }
        __syncthreads();
    }

    // ---- epilogue: row sums -> inv; write out; store inv for norm pass ----
    sa += __shfl_xor_sync(0xffffffffu, sa, 1);
    sa += __shfl_xor_sync(0xffffffffu, sa, 2);
    sb += __shfl_xor_sync(0xffffffffu, sb, 1);
    sb += __shfl_xor_sync(0xffffffffu, sb, 2);
    const float inva = (sa > 0.f) ? (1.0f / sa) : 0.f;
    const float invb = (sb > 0.f) ? (1.0f / sb) : 0.f;
    if (i == 0) {
        g_inv[(size_t)bh * S_ + q0 + qw + g]     = inva;
        g_inv[(size_t)bh * S_ + q0 + qw + g + 8] = invb;
    }

    if (outp) {
        float* orowA = outp + ((size_t)bh * S_ + q0 + qw + g) * D_ + 2 * i;
        float* orowB = orowA + 8 * D_;
        #pragma unroll
        for (int dblk = 0; dblk < 8; ++dblk) {
            *(float2*)&orowA[dblk * 8] = make_float2(o[dblk][0] * inva, o[dblk][1] * inva);
            *(float2*)&orowB[dblk * 8] = make_float2(o[dblk][2] * invb, o[dblk][3] * invb);
        }
    }
}

// ============ norm pass: attn[row][col] = float(e_fp16) * inv, fully coalesced ============
// word u within a row maps to column: (u>>4)*32 + ((u>>2)&3)*8 + (u&3)*2
// each thread handles one uint4 = words 4v..4v+3 (same group, same a, b=0..3) -> 8 consecutive cols
__global__ void norm_kernel(float* __restrict__ attn) {
    size_t t = (size_t)blockIdx.x * blockDim.x + threadIdx.x;   // uint4 index
    size_t row = t >> 8;                                        // 256 uint4 per row
    int v = (int)(t & 255);
    float inv = __ldg(&g_inv[row]);
    uint4 w = __ldcs((const uint4*)g_ebuf + t);
    int col = (v >> 2) * 32 + (v & 3) * 8;
    float2 f0 = unpack_h2(w.x), f1 = unpack_h2(w.y);
    float2 f2 = unpack_h2(w.z), f3 = unpack_h2(w.w);
    float* arow = attn + row * S_ + col;
    __stcs((float4*)arow,       make_float4(f0.x * inv, f0.y * inv, f1.x * inv, f1.y * inv));
    __stcs((float4*)(arow + 4), make_float4(f2.x * inv, f2.y * inv, f3.x * inv, f3.y * inv));
}

extern "C" void kernel_launch(void* const* d_in, const int* in_sizes, int n_in,
                              void* d_out, int out_size)
{
    const float* Q    = (const float*)d_in[0];
    const float* K    = (const float*)d_in[1];
    const float* V    = (const float*)d_in[2];
    const int*   mask = (const int*)d_in[3];

    const size_t OUT_E  = (size_t)B_ * H_ * S_ * D_;
    const size_t ATTN_E = (size_t)B_ * H_ * S_ * S_;
    float* o = nullptr; float* a = nullptr;
    if ((size_t)out_size >= OUT_E + ATTN_E) { o = (float*)d_out; a = (float*)d_out + OUT_E; }
    else if ((size_t)out_size == ATTN_E)    { a = (float*)d_out; }
    else                                    { o = (float*)d_out; }

    maskbits_kernel<<<(B_ * S_ * (S_ / 32)) / 256, 256>>>(mask);
    conv_k<<<(B_ * H_ * S_ * (D_ / 4)) / 256, 256>>>(K);
    conv_v<<<dim3(NKT, B_ * H_), 256>>>(V);

    cudaFuncSetAttribute(attn_fused, cudaFuncAttributeMaxDynamicSharedMemorySize, SMEM_F);

    dim3 grid(S_ / 128, B_ * H_);
    attn_fused<<<grid, THREADS, SMEM_F>>>(Q, o);

    if (a) {
        size_t n4 = (size_t)B_ * H_ * S_ * 256;     // uint4 count
        norm_kernel<<<(unsigned)(n4 / 256), 256>>>(a);
    }
}

// round 15
// speedup vs baseline: 1.5540x; 1.0737x over previous
#include <cuda_runtime.h>
#include <cuda_fp16.h>

typedef unsigned int u32;

#define B_ 4
#define H_ 16
#define S_ 2048
#define D_ 64
#define NKT 16
#define THREADS 256
#define KQ_STR 36      // u32 per K smem row (144B stride; conflict-free ldmatrix)
#define VT_STR 68      // u32 per Vt smem row (272B stride; conflict-free ldmatrix)

__device__ u32   g_mbits[(size_t)B_ * S_ * (S_ / 32)];     // 2 MB mask bitfield
__device__ float g_inv[(size_t)B_ * H_ * S_];              // per-row 1/sum
__device__ u32   g_ebuf[(size_t)B_ * H_ * S_ * (S_ / 2)];  // 0.54 GB fp16x2 e-buffer
// pre-converted operands (hi plane only), tile-major
__device__ u32   g_khi[(size_t)B_ * H_ * S_ * 32];         // [bh][s][32 u32]
__device__ u32   g_vthi[(size_t)B_ * H_ * NKT * 4096];     // [bh][kt][64 d][64 kp]

#define KBUF   (128 * KQ_STR * 4)                          // 18432 B
#define VBUF   (64 * VT_STR * 4)                           // 17408 B
#define SMEM_F (2 * KBUF + 2 * VBUF)                       // 71680 B -> 2 CTAs/SM
#define VOFF   (2 * KBUF)

#define QSCALE 0.1803368801f                               // 0.125 * log2(e)

__device__ __forceinline__ void mma16816(float c[4], const u32 a[4], u32 b0, u32 b1) {
    asm volatile("mma.sync.aligned.m16n8k16.row.col.f32.f16.f16.f32 "
                 "{%0,%1,%2,%3}, {%4,%5,%6,%7}, {%8,%9}, {%0,%1,%2,%3};"
                 : "+f"(c[0]), "+f"(c[1]), "+f"(c[2]), "+f"(c[3])
                 : "r"(a[0]), "r"(a[1]), "r"(a[2]), "r"(a[3]), "r"(b0), "r"(b1));
}

__device__ __forceinline__ void ldm4(u32* r, u32 addr) {
    asm volatile("ldmatrix.sync.aligned.m8n8.x4.shared.b16 {%0,%1,%2,%3}, [%4];"
                 : "=r"(r[0]), "=r"(r[1]), "=r"(r[2]), "=r"(r[3]) : "r"(addr));
}

__device__ __forceinline__ u32 smem_u32(const void* p) {
    return (u32)__cvta_generic_to_shared(p);
}

__device__ __forceinline__ void cpa16(u32 dst, const void* src) {
    asm volatile("cp.async.cg.shared.global [%0], [%1], 16;" :: "r"(dst), "l"(src));
}
#define CP_COMMIT() asm volatile("cp.async.commit_group;" ::: "memory")
#define CP_WAIT1()  asm volatile("cp.async.wait_group 1;" ::: "memory")
#define CP_WAIT0()  asm volatile("cp.async.wait_group 0;" ::: "memory")

__device__ __forceinline__ void stcs64(u32* p, u32 a, u32 b) {
    asm volatile("st.global.cs.v2.u32 [%0], {%1,%2};" :: "l"(p), "r"(a), "r"(b) : "memory");
}

__device__ __forceinline__ void split2(float x, float y, u32& h, u32& l) {
    __half2 H = __floats2half2_rn(x, y);
    h = *reinterpret_cast<u32*>(&H);
    float2 f = __half22float2(H);
    __half2 L = __floats2half2_rn(x - f.x, y - f.y);
    l = *reinterpret_cast<u32*>(&L);
}
__device__ __forceinline__ u32 pack_h2(float x, float y) {
    __half2 H = __floats2half2_rn(x, y);
    return *reinterpret_cast<u32*>(&H);
}
__device__ __forceinline__ float2 unpack_h2(u32 v) {
    return __half22float2(*reinterpret_cast<__half2*>(&v));
}

__global__ void maskbits_kernel(const int* __restrict__ mask) {
    int w = blockIdx.x * blockDim.x + threadIdx.x;
    const int4* src = (const int4*)mask + (size_t)w * 8;
    u32 bits = 0;
    #pragma unroll
    for (int i = 0; i < 8; ++i) {
        int4 v = src[i];
        bits |= (v.x != 0 ? 1u : 0u) << (i * 4);
        bits |= (v.y != 0 ? 1u : 0u) << (i * 4 + 1);
        bits |= (v.z != 0 ? 1u : 0u) << (i * 4 + 2);
        bits |= (v.w != 0 ? 1u : 0u) << (i * 4 + 3);
    }
    g_mbits[w] = bits;
}

__global__ void conv_k(const float* __restrict__ K) {
    size_t idx = (size_t)blockIdx.x * blockDim.x + threadIdx.x;
    float4 v = ((const float4*)K)[idx];
    ((uint2*)g_khi)[idx] = make_uint2(pack_h2(v.x, v.y), pack_h2(v.z, v.w));
}

__global__ void conv_v(const float* __restrict__ V) {
    __shared__ u32 hi[64 * 64];
    const int kt = blockIdx.x, bh = blockIdx.y, tid = threadIdx.x;
    const float4* s4 = (const float4*)(V + ((size_t)bh * S_ + kt * 128) * D_);
    #pragma unroll
    for (int it = 0; it < 4; ++it) {
        int idx = it * THREADS + tid;
        int d4 = idx & 15, kp = idx >> 4;
        float4 a = s4[(2 * kp) * 16 + d4];
        float4 b = s4[(2 * kp + 1) * 16 + d4];
        float av[4] = {a.x, a.y, a.z, a.w};
        float bv[4] = {b.x, b.y, b.z, b.w};
        #pragma unroll
        for (int dd0 = 0; dd0 < 4; ++dd0) {
            int dd = (dd0 + d4) & 3;
            hi[(4 * d4 + dd) * 64 + kp] = pack_h2(av[dd], bv[dd]);
        }
    }
    __syncthreads();
    uint4* gh = (uint4*)(g_vthi + ((size_t)bh * NKT + kt) * 4096);
    #pragma unroll
    for (int it = 0; it < 4; ++it) {
        int idx = it * THREADS + tid;
        gh[idx] = ((uint4*)hi)[idx];
    }
}

__device__ __forceinline__ void stage_k_async(const u32* __restrict__ ghi, u32 smhi, int tid) {
    #pragma unroll
    for (int it = 0; it < 4; ++it) {
        int idx = it * THREADS + tid;
        int r = idx >> 3, c = idx & 7;
        cpa16(smhi + (u32)((r * KQ_STR + c * 4) * 4), ghi + (size_t)idx * 4);
    }
}
__device__ __forceinline__ void stage_v_async(const u32* __restrict__ ghi, u32 smhi, int tid) {
    #pragma unroll
    for (int it = 0; it < 4; ++it) {
        int idx = it * THREADS + tid;
        int r = idx >> 4, c = idx & 15;
        cpa16(smhi + (u32)((r * VT_STR + c * 4) * 4), ghi + (size_t)idx * 4);
    }
}

// ============ fused kernel: QK -> e (regs) -> {e-buffer store, PV mma} + out ============
// e-buffer word order within each 16-word group: idx = kc2*8 + i*2 + mid
//   (mid 0 = low col-octet, 1 = high) -> each thread stores uint2 per (row, kc2)
__global__ __launch_bounds__(THREADS, 2)
void attn_fused(const float* __restrict__ Q, float* __restrict__ outp)
{
    extern __shared__ char sm[];

    const int tid = threadIdx.x, wid = tid >> 5, lane = tid & 31;
    const int g = lane >> 2, i = lane & 3;
    const int trow = lane & 7, tmat = lane >> 3;
    const int q0 = blockIdx.x * 128, bh = blockIdx.y, b = bh >> 4;
    const int qw = wid * 16;

    const u32* KbH = g_khi + (size_t)bh * S_ * 32;
    const u32* VbH = g_vthi + (size_t)bh * NKT * 4096;

    // Q fragments from gmem, scale*log2e folded (scores in log2 domain)
    u32 qh[4][4], ql[4][4];
    {
        const float* qa = Q + ((size_t)bh * S_ + q0 + qw + g) * D_;
        const float* qb = qa + 8 * D_;
        #pragma unroll
        for (int kc = 0; kc < 4; ++kc) {
            float2 a0 = *(const float2*)(qa + 16 * kc + 2 * i);
            float2 a1 = *(const float2*)(qa + 16 * kc + 8 + 2 * i);
            float2 b0 = *(const float2*)(qb + 16 * kc + 2 * i);
            float2 b1 = *(const float2*)(qb + 16 * kc + 8 + 2 * i);
            split2(a0.x * QSCALE, a0.y * QSCALE, qh[kc][0], ql[kc][0]);
            split2(b0.x * QSCALE, b0.y * QSCALE, qh[kc][1], ql[kc][1]);
            split2(a1.x * QSCALE, a1.y * QSCALE, qh[kc][2], ql[kc][2]);
            split2(b1.x * QSCALE, b1.y * QSCALE, qh[kc][3], ql[kc][3]);
        }
    }

    const u32* mra = g_mbits + (size_t)(b * S_ + q0 + qw + g) * (S_ / 32);
    const u32* mrb = mra + 8 * (S_ / 32);
    u32* ebA = g_ebuf + (size_t)(bh * S_ + q0 + qw + g) * (S_ / 2);
    u32* ebB = ebA + 8 * (S_ / 2);

    float sa = 0.f, sb = 0.f;
    float o[8][4];
    #pragma unroll
    for (int d = 0; d < 8; ++d) o[d][0] = o[d][1] = o[d][2] = o[d][3] = 0.f;

    const u32 smbase = smem_u32(sm);
    stage_k_async(KbH, smbase, tid);
    stage_v_async(VbH, smbase + VOFF, tid);
    CP_COMMIT();

    for (int kt = 0; kt < NKT; ++kt) {
        if (kt + 1 < NKT) {
            stage_k_async(KbH + (size_t)(kt + 1) * 128 * 32,
                          smbase + ((kt + 1) & 1) * KBUF, tid);
            stage_v_async(VbH + (size_t)(kt + 1) * 4096,
                          smbase + VOFF + ((kt + 1) & 1) * VBUF, tid);
            CP_COMMIT();
            CP_WAIT1();
        } else {
            CP_WAIT0();
        }
        __syncthreads();

        const u32 khi_u  = smbase + (kt & 1) * KBUF;
        const u32 vthi_u = smbase + VOFF + (kt & 1) * VBUF;

        const uint4 wa4 = *(const uint4*)(mra + kt * 4);
        const uint4 wb4 = *(const uint4*)(mrb + kt * 4);
        const u32 waw[4] = {wa4.x, wa4.y, wa4.z, wa4.w};
        const u32 wbw[4] = {wb4.x, wb4.y, wb4.z, wb4.w};

        #pragma unroll
        for (int sub = 0; sub < 2; ++sub) {
            #pragma unroll
            for (int jq = 0; jq < 2; ++jq) {
                float c[4][4];
                #pragma unroll
                for (int j = 0; j < 4; ++j)
                    c[j][0] = c[j][1] = c[j][2] = c[j][3] = 0.f;

                // ---- QK MMAs ----
                #pragma unroll
                for (int j4 = 0; j4 < 4; ++j4) {
                    int nrow = sub * 64 + jq * 32 + j4 * 8 + trow;
                    u32 rb = (u32)((nrow * KQ_STR + tmat * 4) * 4);
                    u32 bhv[8];
                    ldm4(&bhv[0], khi_u + rb);
                    ldm4(&bhv[4], khi_u + rb + 64);
                    #pragma unroll
                    for (int kc = 0; kc < 4; ++kc) {
                        mma16816(c[j4], qh[kc], bhv[2 * kc], bhv[2 * kc + 1]);
                        mma16816(c[j4], ql[kc], bhv[2 * kc], bhv[2 * kc + 1]);
                    }
                }

                // ---- mask + exp2 (scores already in log2 domain) ----
                const u32 was = waw[sub * 2 + jq] >> (2 * i);
                const u32 wbs = wbw[sub * 2 + jq] >> (2 * i);
                #pragma unroll
                for (int j4 = 0; j4 < 4; ++j4) {
                    u32 ba = was >> (j4 * 8), bb = wbs >> (j4 * 8);
                    float e0 = (ba & 1u) ? exp2f(c[j4][0]) : 0.f;
                    float e1 = (ba & 2u) ? exp2f(c[j4][1]) : 0.f;
                    float e2 = (bb & 1u) ? exp2f(c[j4][2]) : 0.f;
                    float e3 = (bb & 2u) ? exp2f(c[j4][3]) : 0.f;
                    sa += e0 + e1;
                    sb += e2 + e3;
                    c[j4][0] = e0; c[j4][1] = e1; c[j4][2] = e2; c[j4][3] = e3;
                }

                // ---- pack e fragments; store to e-buffer (uint2); PV mma from regs ----
                const int grp = kt * 64 + sub * 32 + jq * 16;
                u32 aa[2][4];
                #pragma unroll
                for (int kc2 = 0; kc2 < 2; ++kc2) {
                    aa[kc2][0] = pack_h2(c[2 * kc2][0],     c[2 * kc2][1]);
                    aa[kc2][1] = pack_h2(c[2 * kc2][2],     c[2 * kc2][3]);
                    aa[kc2][2] = pack_h2(c[2 * kc2 + 1][0], c[2 * kc2 + 1][1]);
                    aa[kc2][3] = pack_h2(c[2 * kc2 + 1][2], c[2 * kc2 + 1][3]);
                    // word order: kc2*8 + i*2 + mid -> adjacent pair per thread
                    stcs64(&ebA[grp + kc2 * 8 + 2 * i], aa[kc2][0], aa[kc2][2]);
                    stcs64(&ebB[grp + kc2 * 8 + 2 * i], aa[kc2][1], aa[kc2][3]);
                }

                #pragma unroll
                for (int dblk = 0; dblk < 8; ++dblk) {
                    u32 rb = (u32)(((dblk * 8 + trow) * VT_STR
                                    + sub * 32 + jq * 16 + tmat * 4) * 4);
                    u32 vh[4];
                    ldm4(vh, vthi_u + rb);
                    #pragma unroll
                    for (int kc2 = 0; kc2 < 2; ++kc2)
                        mma16816(o[dblk], aa[kc2], vh[2 * kc2], vh[2 * kc2 + 1]);
                }
            }
        }
        __syncthreads();
    }

    // ---- epilogue ----
    sa += __shfl_xor_sync(0xffffffffu, sa, 1);
    sa += __shfl_xor_sync(0xffffffffu, sa, 2);
    sb += __shfl_xor_sync(0xffffffffu, sb, 1);
    sb += __shfl_xor_sync(0xffffffffu, sb, 2);
    const float inva = (sa > 0.f) ? (1.0f / sa) : 0.f;
    const float invb = (sb > 0.f) ? (1.0f / sb) : 0.f;
    if (i == 0) {
        g_inv[(size_t)bh * S_ + q0 + qw + g]     = inva;
        g_inv[(size_t)bh * S_ + q0 + qw + g + 8] = invb;
    }

    if (outp) {
        float* orowA = outp + ((size_t)bh * S_ + q0 + qw + g) * D_ + 2 * i;
        float* orowB = orowA + 8 * D_;
        #pragma unroll
        for (int dblk = 0; dblk < 8; ++dblk) {
            *(float2*)&orowA[dblk * 8] = make_float2(o[dblk][0] * inva, o[dblk][1] * inva);
            *(float2*)&orowB[dblk * 8] = make_float2(o[dblk][2] * invb, o[dblk][3] * invb);
        }
    }
}

// ============ norm pass: attn[row][col] = float(e_fp16) * inv ============
// word u in row (order kc2*8 + i*2 + mid): col = (16*(u>>4) + ((u>>3)&1)*8 + (u&1)*4 + ((u>>1)&3))*2
// thread t handles uint4 = words 4v..4v+3: same (gq,kc2), i in {i0,i0+1}, mid in {0,1}
//   i0 = 2*(v&1), kc2 = (v>>1)&1, gq = v>>2
//   -> float4 at col1 = 2*(gq*16 + kc2*8 + i0) from (w.x, w.z), float4 at col1+8 from (w.y, w.w)
__global__ void norm_kernel(float* __restrict__ attn) {
    size_t t = (size_t)blockIdx.x * blockDim.x + threadIdx.x;   // uint4 index
    size_t row = t >> 8;                                        // 256 uint4 per row
    int v = (int)(t & 255);
    float inv = __ldg(&g_inv[row]);
    uint4 w = __ldcs((const uint4*)g_ebuf + t);
    int col1 = 2 * ((v >> 2) * 16 + ((v >> 1) & 1) * 8 + (v & 1) * 2);
    float2 fx = unpack_h2(w.x), fy = unpack_h2(w.y);
    float2 fz = unpack_h2(w.z), fw = unpack_h2(w.w);
    float* arow = attn + row * S_;
    __stcs((float4*)(arow + col1),
           make_float4(fx.x * inv, fx.y * inv, fz.x * inv, fz.y * inv));
    __stcs((float4*)(arow + col1 + 8),
           make_float4(fy.x * inv, fy.y * inv, fw.x * inv, fw.y * inv));
}

extern "C" void kernel_launch(void* const* d_in, const int* in_sizes, int n_in,
                              void* d_out, int out_size)
{
    const float* Q    = (const float*)d_in[0];
    const float* K    = (const float*)d_in[1];
    const float* V    = (const float*)d_in[2];
    const int*   mask = (const int*)d_in[3];

    const size_t OUT_E  = (size_t)B_ * H_ * S_ * D_;
    const size_t ATTN_E = (size_t)B_ * H_ * S_ * S_;
    float* o = nullptr; float* a = nullptr;
    if ((size_t)out_size >= OUT_E + ATTN_E) { o = (float*)d_out; a = (float*)d_out + OUT_E; }
    else if ((size_t)out_size == ATTN_E)    { a = (float*)d_out; }
    else                                    { o = (float*)d_out; }

    maskbits_kernel<<<(B_ * S_ * (S_ / 32)) / 256, 256>>>(mask);
    conv_k<<<(B_ * H_ * S_ * (D_ / 4)) / 256, 256>>>(K);
    conv_v<<<dim3(NKT, B_ * H_), 256>>>(V);

    cudaFuncSetAttribute(attn_fused, cudaFuncAttributeMaxDynamicSharedMemorySize, SMEM_F);

    dim3 grid(S_ / 128, B_ * H_);
    attn_fused<<<grid, THREADS, SMEM_F>>>(Q, o);

    if (a) {
        size_t n4 = (size_t)B_ * H_ * S_ * 256;     // uint4 count
        norm_kernel<<<(unsigned)(n4 / 256), 256>>>(a);
    }
}

// round 16
// speedup vs baseline: 1.6355x; 1.0524x over previous
#include <cuda_runtime.h>
#include <cuda_fp16.h>

typedef unsigned int u32;

#define B_ 4
#define H_ 16
#define S_ 2048
#define D_ 64
#define NKT 16
#define THREADS 256
#define KQ_STR 36      // u32 per K smem row (144B stride; conflict-free ldmatrix)
#define VT_STR 68      // u32 per Vt smem row (272B stride; conflict-free ldmatrix)

__device__ u32   g_mbits[(size_t)B_ * S_ * (S_ / 32)];     // 2 MB mask bitfield
__device__ float g_inv[(size_t)B_ * H_ * S_];              // per-row 1/sum
__device__ u32   g_ebuf[(size_t)B_ * H_ * S_ * (S_ / 2)];  // 0.54 GB fp16x2 e-buffer
// pre-converted operands (hi plane only), tile-major
__device__ u32   g_khi[(size_t)B_ * H_ * S_ * 32];         // [bh][s][32 u32]
__device__ u32   g_vthi[(size_t)B_ * H_ * NKT * 4096];     // [bh][kt][64 d][64 kp]

#define KBUF   (128 * KQ_STR * 4)                          // 18432 B
#define VBUF   (64 * VT_STR * 4)                           // 17408 B
#define SMEM_F (2 * KBUF + 2 * VBUF)                       // 71680 B -> 2 CTAs/SM
#define VOFF   (2 * KBUF)

#define QSCALE 0.1803368801f                               // 0.125 * log2(e)

__device__ __forceinline__ void mma16816(float c[4], const u32 a[4], u32 b0, u32 b1) {
    asm volatile("mma.sync.aligned.m16n8k16.row.col.f32.f16.f16.f32 "
                 "{%0,%1,%2,%3}, {%4,%5,%6,%7}, {%8,%9}, {%0,%1,%2,%3};"
                 : "+f"(c[0]), "+f"(c[1]), "+f"(c[2]), "+f"(c[3])
                 : "r"(a[0]), "r"(a[1]), "r"(a[2]), "r"(a[3]), "r"(b0), "r"(b1));
}

__device__ __forceinline__ void ldm4(u32* r, u32 addr) {
    asm volatile("ldmatrix.sync.aligned.m8n8.x4.shared.b16 {%0,%1,%2,%3}, [%4];"
                 : "=r"(r[0]), "=r"(r[1]), "=r"(r[2]), "=r"(r[3]) : "r"(addr));
}

__device__ __forceinline__ u32 smem_u32(const void* p) {
    return (u32)__cvta_generic_to_shared(p);
}

__device__ __forceinline__ void cpa16(u32 dst, const void* src) {
    asm volatile("cp.async.cg.shared.global [%0], [%1], 16;" :: "r"(dst), "l"(src));
}
#define CP_COMMIT() asm volatile("cp.async.commit_group;" ::: "memory")
#define CP_WAIT1()  asm volatile("cp.async.wait_group 1;" ::: "memory")
#define CP_WAIT0()  asm volatile("cp.async.wait_group 0;" ::: "memory")

__device__ __forceinline__ void stcs64(u32* p, u32 a, u32 b) {
    asm volatile("st.global.cs.v2.u32 [%0], {%1,%2};" :: "l"(p), "r"(a), "r"(b) : "memory");
}

__device__ __forceinline__ u32 pack_h2(float x, float y) {
    __half2 H = __floats2half2_rn(x, y);
    return *reinterpret_cast<u32*>(&H);
}
__device__ __forceinline__ float2 unpack_h2(u32 v) {
    return __half22float2(*reinterpret_cast<__half2*>(&v));
}

__global__ void maskbits_kernel(const int* __restrict__ mask) {
    int w = blockIdx.x * blockDim.x + threadIdx.x;
    const int4* src = (const int4*)mask + (size_t)w * 8;
    u32 bits = 0;
    #pragma unroll
    for (int i = 0; i < 8; ++i) {
        int4 v = src[i];
        bits |= (v.x != 0 ? 1u : 0u) << (i * 4);
        bits |= (v.y != 0 ? 1u : 0u) << (i * 4 + 1);
        bits |= (v.z != 0 ? 1u : 0u) << (i * 4 + 2);
        bits |= (v.w != 0 ? 1u : 0u) << (i * 4 + 3);
    }
    g_mbits[w] = bits;
}

__global__ void conv_k(const float* __restrict__ K) {
    size_t idx = (size_t)blockIdx.x * blockDim.x + threadIdx.x;
    float4 v = ((const float4*)K)[idx];
    ((uint2*)g_khi)[idx] = make_uint2(pack_h2(v.x, v.y), pack_h2(v.z, v.w));
}

__global__ void conv_v(const float* __restrict__ V) {
    __shared__ u32 hi[64 * 64];
    const int kt = blockIdx.x, bh = blockIdx.y, tid = threadIdx.x;
    const float4* s4 = (const float4*)(V + ((size_t)bh * S_ + kt * 128) * D_);
    #pragma unroll
    for (int it = 0; it < 4; ++it) {
        int idx = it * THREADS + tid;
        int d4 = idx & 15, kp = idx >> 4;
        float4 a = s4[(2 * kp) * 16 + d4];
        float4 b = s4[(2 * kp + 1) * 16 + d4];
        float av[4] = {a.x, a.y, a.z, a.w};
        float bv[4] = {b.x, b.y, b.z, b.w};
        #pragma unroll
        for (int dd0 = 0; dd0 < 4; ++dd0) {
            int dd = (dd0 + d4) & 3;
            hi[(4 * d4 + dd) * 64 + kp] = pack_h2(av[dd], bv[dd]);
        }
    }
    __syncthreads();
    uint4* gh = (uint4*)(g_vthi + ((size_t)bh * NKT + kt) * 4096);
    #pragma unroll
    for (int it = 0; it < 4; ++it) {
        int idx = it * THREADS + tid;
        gh[idx] = ((uint4*)hi)[idx];
    }
}

__device__ __forceinline__ void stage_k_async(const u32* __restrict__ ghi, u32 smhi, int tid) {
    #pragma unroll
    for (int it = 0; it < 4; ++it) {
        int idx = it * THREADS + tid;
        int r = idx >> 3, c = idx & 7;
        cpa16(smhi + (u32)((r * KQ_STR + c * 4) * 4), ghi + (size_t)idx * 4);
    }
}
__device__ __forceinline__ void stage_v_async(const u32* __restrict__ ghi, u32 smhi, int tid) {
    #pragma unroll
    for (int it = 0; it < 4; ++it) {
        int idx = it * THREADS + tid;
        int r = idx >> 4, c = idx & 15;
        cpa16(smhi + (u32)((r * VT_STR + c * 4) * 4), ghi + (size_t)idx * 4);
    }
}

// ============ fused kernel: QK (fp16) -> e (regs) -> {e-buffer store, PV mma} + out ============
__global__ __launch_bounds__(THREADS, 2)
void attn_fused(const float* __restrict__ Q, float* __restrict__ outp)
{
    extern __shared__ char sm[];

    const int tid = threadIdx.x, wid = tid >> 5, lane = tid & 31;
    const int g = lane >> 2, i = lane & 3;
    const int trow = lane & 7, tmat = lane >> 3;
    const int q0 = blockIdx.x * 128, bh = blockIdx.y, b = bh >> 4;
    const int qw = wid * 16;

    const u32* KbH = g_khi + (size_t)bh * S_ * 32;
    const u32* VbH = g_vthi + (size_t)bh * NKT * 4096;

    // Q fragments (hi only) from gmem, scale*log2e folded
    u32 qh[4][4];
    {
        const float* qa = Q + ((size_t)bh * S_ + q0 + qw + g) * D_;
        const float* qb = qa + 8 * D_;
        #pragma unroll
        for (int kc = 0; kc < 4; ++kc) {
            float2 a0 = *(const float2*)(qa + 16 * kc + 2 * i);
            float2 a1 = *(const float2*)(qa + 16 * kc + 8 + 2 * i);
            float2 b0 = *(const float2*)(qb + 16 * kc + 2 * i);
            float2 b1 = *(const float2*)(qb + 16 * kc + 8 + 2 * i);
            qh[kc][0] = pack_h2(a0.x * QSCALE, a0.y * QSCALE);
            qh[kc][1] = pack_h2(b0.x * QSCALE, b0.y * QSCALE);
            qh[kc][2] = pack_h2(a1.x * QSCALE, a1.y * QSCALE);
            qh[kc][3] = pack_h2(b1.x * QSCALE, b1.y * QSCALE);
        }
    }

    const u32* mra = g_mbits + (size_t)(b * S_ + q0 + qw + g) * (S_ / 32);
    const u32* mrb = mra + 8 * (S_ / 32);
    u32* ebA = g_ebuf + (size_t)(bh * S_ + q0 + qw + g) * (S_ / 2);
    u32* ebB = ebA + 8 * (S_ / 2);

    float sa = 0.f, sb = 0.f;
    float o[8][4];
    #pragma unroll
    for (int d = 0; d < 8; ++d) o[d][0] = o[d][1] = o[d][2] = o[d][3] = 0.f;

    const u32 smbase = smem_u32(sm);
    stage_k_async(KbH, smbase, tid);
    stage_v_async(VbH, smbase + VOFF, tid);
    CP_COMMIT();

    for (int kt = 0; kt < NKT; ++kt) {
        if (kt + 1 < NKT) {
            stage_k_async(KbH + (size_t)(kt + 1) * 128 * 32,
                          smbase + ((kt + 1) & 1) * KBUF, tid);
            stage_v_async(VbH + (size_t)(kt + 1) * 4096,
                          smbase + VOFF + ((kt + 1) & 1) * VBUF, tid);
            CP_COMMIT();
            CP_WAIT1();
        } else {
            CP_WAIT0();
        }
        __syncthreads();

        const u32 khi_u  = smbase + (kt & 1) * KBUF;
        const u32 vthi_u = smbase + VOFF + (kt & 1) * VBUF;

        const uint4 wa4 = *(const uint4*)(mra + kt * 4);
        const uint4 wb4 = *(const uint4*)(mrb + kt * 4);
        const u32 waw[4] = {wa4.x, wa4.y, wa4.z, wa4.w};
        const u32 wbw[4] = {wb4.x, wb4.y, wb4.z, wb4.w};

        #pragma unroll
        for (int sub = 0; sub < 2; ++sub) {
            #pragma unroll
            for (int jq = 0; jq < 2; ++jq) {
                float c[4][4];
                #pragma unroll
                for (int j = 0; j < 4; ++j)
                    c[j][0] = c[j][1] = c[j][2] = c[j][3] = 0.f;

                // ---- QK MMAs (fp16 single product) ----
                #pragma unroll
                for (int j4 = 0; j4 < 4; ++j4) {
                    int nrow = sub * 64 + jq * 32 + j4 * 8 + trow;
                    u32 rb = (u32)((nrow * KQ_STR + tmat * 4) * 4);
                    u32 bhv[8];
                    ldm4(&bhv[0], khi_u + rb);
                    ldm4(&bhv[4], khi_u + rb + 64);
                    #pragma unroll
                    for (int kc = 0; kc < 4; ++kc)
                        mma16816(c[j4], qh[kc], bhv[2 * kc], bhv[2 * kc + 1]);
                }

                // ---- mask + exp2 (scores in log2 domain) ----
                const u32 was = waw[sub * 2 + jq] >> (2 * i);
                const u32 wbs = wbw[sub * 2 + jq] >> (2 * i);
                #pragma unroll
                for (int j4 = 0; j4 < 4; ++j4) {
                    u32 ba = was >> (j4 * 8), bb = wbs >> (j4 * 8);
                    float e0 = (ba & 1u) ? exp2f(c[j4][0]) : 0.f;
                    float e1 = (ba & 2u) ? exp2f(c[j4][1]) : 0.f;
                    float e2 = (bb & 1u) ? exp2f(c[j4][2]) : 0.f;
                    float e3 = (bb & 2u) ? exp2f(c[j4][3]) : 0.f;
                    sa += e0 + e1;
                    sb += e2 + e3;
                    c[j4][0] = e0; c[j4][1] = e1; c[j4][2] = e2; c[j4][3] = e3;
                }

                // ---- pack e fragments; store to e-buffer (uint2); PV mma from regs ----
                const int grp = kt * 64 + sub * 32 + jq * 16;
                u32 aa[2][4];
                #pragma unroll
                for (int kc2 = 0; kc2 < 2; ++kc2) {
                    aa[kc2][0] = pack_h2(c[2 * kc2][0],     c[2 * kc2][1]);
                    aa[kc2][1] = pack_h2(c[2 * kc2][2],     c[2 * kc2][3]);
                    aa[kc2][2] = pack_h2(c[2 * kc2 + 1][0], c[2 * kc2 + 1][1]);
                    aa[kc2][3] = pack_h2(c[2 * kc2 + 1][2], c[2 * kc2 + 1][3]);
                    stcs64(&ebA[grp + kc2 * 8 + 2 * i], aa[kc2][0], aa[kc2][2]);
                    stcs64(&ebB[grp + kc2 * 8 + 2 * i], aa[kc2][1], aa[kc2][3]);
                }

                #pragma unroll
                for (int dblk = 0; dblk < 8; ++dblk) {
                    u32 rb = (u32)(((dblk * 8 + trow) * VT_STR
                                    + sub * 32 + jq * 16 + tmat * 4) * 4);
                    u32 vh[4];
                    ldm4(vh, vthi_u + rb);
                    #pragma unroll
                    for (int kc2 = 0; kc2 < 2; ++kc2)
                        mma16816(o[dblk], aa[kc2], vh[2 * kc2], vh[2 * kc2 + 1]);
                }
            }
        }
        __syncthreads();
    }

    // ---- epilogue ----
    sa += __shfl_xor_sync(0xffffffffu, sa, 1);
    sa += __shfl_xor_sync(0xffffffffu, sa, 2);
    sb += __shfl_xor_sync(0xffffffffu, sb, 1);
    sb += __shfl_xor_sync(0xffffffffu, sb, 2);
    const float inva = (sa > 0.f) ? (1.0f / sa) : 0.f;
    const float invb = (sb > 0.f) ? (1.0f / sb) : 0.f;
    if (i == 0) {
        g_inv[(size_t)bh * S_ + q0 + qw + g]     = inva;
        g_inv[(size_t)bh * S_ + q0 + qw + g + 8] = invb;
    }

    if (outp) {
        float* orowA = outp + ((size_t)bh * S_ + q0 + qw + g) * D_ + 2 * i;
        float* orowB = orowA + 8 * D_;
        #pragma unroll
        for (int dblk = 0; dblk < 8; ++dblk) {
            *(float2*)&orowA[dblk * 8] = make_float2(o[dblk][0] * inva, o[dblk][1] * inva);
            *(float2*)&orowB[dblk * 8] = make_float2(o[dblk][2] * invb, o[dblk][3] * invb);
        }
    }
}

// ============ norm pass: attn[row][col] = float(e_fp16) * inv ============
__global__ void norm_kernel(float* __restrict__ attn) {
    size_t t = (size_t)blockIdx.x * blockDim.x + threadIdx.x;   // uint4 index
    size_t row = t >> 8;                                        // 256 uint4 per row
    int v = (int)(t & 255);
    float inv = __ldg(&g_inv[row]);
    uint4 w = __ldcs((const uint4*)g_ebuf + t);
    int col1 = 2 * ((v >> 2) * 16 + ((v >> 1) & 1) * 8 + (v & 1) * 2);
    float2 fx = unpack_h2(w.x), fy = unpack_h2(w.y);
    float2 fz = unpack_h2(w.z), fw = unpack_h2(w.w);
    float* arow = attn + row * S_;
    __stcs((float4*)(arow + col1),
           make_float4(fx.x * inv, fx.y * inv, fz.x * inv, fz.y * inv));
    __stcs((float4*)(arow + col1 + 8),
           make_float4(fy.x * inv, fy.y * inv, fw.x * inv, fw.y * inv));
}

extern "C" void kernel_launch(void* const* d_in, const int* in_sizes, int n_in,
                              void* d_out, int out_size)
{
    const float* Q    = (const float*)d_in[0];
    const float* K    = (const float*)d_in[1];
    const float* V    = (const float*)d_in[2];
    const int*   mask = (const int*)d_in[3];

    const size_t OUT_E  = (size_t)B_ * H_ * S_ * D_;
    const size_t ATTN_E = (size_t)B_ * H_ * S_ * S_;
    float* o = nullptr; float* a = nullptr;
    if ((size_t)out_size >= OUT_E + ATTN_E) { o = (float*)d_out; a = (float*)d_out + OUT_E; }
    else if ((size_t)out_size == ATTN_E)    { a = (float*)d_out; }
    else                                    { o = (float*)d_out; }

    maskbits_kernel<<<(B_ * S_ * (S_ / 32)) / 256, 256>>>(mask);
    conv_k<<<(B_ * H_ * S_ * (D_ / 4)) / 256, 256>>>(K);
    conv_v<<<dim3(NKT, B_ * H_), 256>>>(V);

    cudaFuncSetAttribute(attn_fused, cudaFuncAttributeMaxDynamicSharedMemorySize, SMEM_F);

    dim3 grid(S_ / 128, B_ * H_);
    attn_fused<<<grid, THREADS, SMEM_F>>>(Q, o);

    if (a) {
        size_t n4 = (size_t)B_ * H_ * S_ * 256;     // uint4 count
        norm_kernel<<<(unsigned)(n4 / 256), 256>>>(a);
    }
}